// round 2
// baseline (speedup 1.0000x reference)
#include <cuda_runtime.h>
#include <math.h>

#define NN 4096
#define DIN 256
#define DOUT 256
#define KH 3
#define CAP 512
#define GEMM_BLOCKS 768   // (DOUT/64) * (NN/64) * KH = 4*64*3

// scratch (device globals: no allocation allowed)
__device__ float g_wx[KH * NN * DOUT];          // 12 MB
__device__ float g_al[KH * NN * 4];
__device__ float g_ar[KH * NN * 4];
__device__ unsigned g_list[NN * CAP];           // 8 MB edge lists
__device__ int g_cnt[NN];

// ---------------------------------------------------------------------------
// Kernel A: fused  [GEMM wx = x @ W_t[k]]  +  [mask compaction -> edge lists]
// blocks [0, 768): gemm tiles;  blocks [768, 768+4096): one row compaction
// ---------------------------------------------------------------------------
__global__ void __launch_bounds__(256)
fused_gemm_compact(const float* __restrict__ x,
                   const float* __restrict__ Wt,
                   const int* __restrict__ supports,
                   const int* __restrict__ atten) {
    __shared__ float As[16][64];
    __shared__ float Bs[16][64];
    __shared__ int s_warp[8];

    int bid = blockIdx.x;
    int tx = threadIdx.x;

    if (bid < GEMM_BLOCKS) {
        // ---------------- GEMM path ----------------
        int k = bid >> 8;            // /256
        int rem = bid & 255;
        int row0 = (rem >> 2) * 64;
        int col0 = (rem & 3) * 64;
        const float* B = Wt + (size_t)k * DIN * DOUT;
        float* C = g_wx + (size_t)k * NN * DOUT;

        int tr = tx >> 4;
        int tc = tx & 15;

        float acc[4][4];
#pragma unroll
        for (int i = 0; i < 4; i++)
#pragma unroll
            for (int j = 0; j < 4; j++) acc[i][j] = 0.f;

        for (int kk = 0; kk < DIN; kk += 16) {
            {
                int r = tx >> 2;
                int c4 = (tx & 3) * 4;
                float4 v = *(const float4*)(x + (size_t)(row0 + r) * DIN + kk + c4);
                As[c4 + 0][r] = v.x;
                As[c4 + 1][r] = v.y;
                As[c4 + 2][r] = v.z;
                As[c4 + 3][r] = v.w;
            }
            {
                int rr = tx >> 4;
                int cc = tx & 15;
                float4 w = *(const float4*)(B + (size_t)(kk + rr) * DOUT + col0 + cc * 4);
                *(float4*)&Bs[rr][cc * 4] = w;
            }
            __syncthreads();
#pragma unroll
            for (int p = 0; p < 16; p++) {
                float4 a = *(float4*)&As[p][tr * 4];
                float4 b = *(float4*)&Bs[p][tc * 4];
                float av[4] = {a.x, a.y, a.z, a.w};
                float bv[4] = {b.x, b.y, b.z, b.w};
#pragma unroll
                for (int i = 0; i < 4; i++)
#pragma unroll
                    for (int j = 0; j < 4; j++) acc[i][j] += av[i] * bv[j];
            }
            __syncthreads();
        }
#pragma unroll
        for (int i = 0; i < 4; i++) {
            float4 v = make_float4(acc[i][0], acc[i][1], acc[i][2], acc[i][3]);
            *(float4*)(C + (size_t)(row0 + tr * 4 + i) * DOUT + col0 + tc * 4) = v;
        }
    } else {
        // ---------------- compaction path ----------------
        int n = bid - GEMM_BLOCKS;
        int lane = tx & 31;
        int wid = tx >> 5;

        const int4* pa0 = (const int4*)(atten + ((size_t)0 * NN + n) * NN);
        const int4* pa1 = (const int4*)(atten + ((size_t)1 * NN + n) * NN);
        const int4* pa2 = (const int4*)(atten + ((size_t)2 * NN + n) * NN);
        const int4* ps0 = (const int4*)(supports + ((size_t)0 * NN + n) * NN);
        const int4* ps1 = (const int4*)(supports + ((size_t)1 * NN + n) * NN);
        const int4* ps2 = (const int4*)(supports + ((size_t)2 * NN + n) * NN);

        unsigned char codes[16];
        int cnt_local = 0;
#pragma unroll
        for (int it = 0; it < 4; it++) {
            int i = tx + it * 256;
            int4 a0 = pa0[i], a1 = pa1[i], a2 = pa2[i];
            int4 q0 = ps0[i], q1 = ps1[i], q2 = ps2[i];
            int aa0[4] = {a0.x, a0.y, a0.z, a0.w};
            int aa1[4] = {a1.x, a1.y, a1.z, a1.w};
            int aa2[4] = {a2.x, a2.y, a2.z, a2.w};
            int qq0[4] = {q0.x, q0.y, q0.z, q0.w};
            int qq1[4] = {q1.x, q1.y, q1.z, q1.w};
            int qq2[4] = {q2.x, q2.y, q2.z, q2.w};
#pragma unroll
            for (int j = 0; j < 4; j++) {
                int code = (aa0[j] ? 1 : 0) | (aa1[j] ? 2 : 0) | (aa2[j] ? 4 : 0) |
                           (qq0[j] ? 8 : 0) | (qq1[j] ? 16 : 0) | (qq2[j] ? 32 : 0);
                codes[it * 4 + j] = (unsigned char)code;
                cnt_local += (code != 0);
            }
        }

        // exclusive prefix sum over 256 threads
        int incl = cnt_local;
#pragma unroll
        for (int o = 1; o < 32; o <<= 1) {
            int t = __shfl_up_sync(0xffffffffu, incl, o);
            if (lane >= o) incl += t;
        }
        if (lane == 31) s_warp[wid] = incl;
        __syncthreads();
        if (tx < 8) {
            int t = s_warp[tx];
            int p = t;
#pragma unroll
            for (int o = 1; o < 8; o <<= 1) {
                int u = __shfl_up_sync(0xffu, p, o);
                if (tx >= o) p += u;
            }
            s_warp[tx] = p - t;
        }
        __syncthreads();
        int off = s_warp[wid] + incl - cnt_local;
        if (tx == 255) g_cnt[n] = min(off + cnt_local, CAP);

        unsigned* lst = g_list + (size_t)n * CAP;
#pragma unroll
        for (int it = 0; it < 4; it++) {
#pragma unroll
            for (int j = 0; j < 4; j++) {
                int c = codes[it * 4 + j];
                if (c) {
                    int m = (tx + it * 256) * 4 + j;
                    if (off < CAP) lst[off] = ((unsigned)m << 6) | (unsigned)c;
                    off++;
                }
            }
        }
    }
}

// ---------------------------------------------------------------------------
// Kernel B: al[k][n][j] = wx[k][n] . W_l[k][j],  ar same with W_r
// ---------------------------------------------------------------------------
__global__ void alar_kernel(const float* __restrict__ Wl,
                            const float* __restrict__ Wr) {
    int k = blockIdx.y;
    int n0 = blockIdx.x * 32;
    __shared__ float sx[32][DOUT + 1];

    const float* wx = g_wx + (size_t)k * NN * DOUT;
    for (int i = threadIdx.x; i < 32 * (DOUT / 4); i += blockDim.x) {
        int r = i / (DOUT / 4);
        int c = i % (DOUT / 4);
        float4 v = *(const float4*)(wx + (size_t)(n0 + r) * DOUT + c * 4);
        sx[r][c * 4 + 0] = v.x;
        sx[r][c * 4 + 1] = v.y;
        sx[r][c * 4 + 2] = v.z;
        sx[r][c * 4 + 3] = v.w;
    }
    __syncthreads();

    int n = threadIdx.x >> 3;
    int j = threadIdx.x & 7;
    const float* w = (j < 4) ? (Wl + (size_t)(k * 4 + j) * DOUT)
                             : (Wr + (size_t)(k * 4 + (j - 4)) * DOUT);
    float s = 0.f;
#pragma unroll 8
    for (int d = 0; d < DOUT; d++) s += sx[n][d] * w[d];

    if (j < 4)
        g_al[((size_t)k * NN + n0 + n) * 4 + j] = s;
    else
        g_ar[((size_t)k * NN + n0 + n) * 4 + (j - 4)] = s;
}

// ---------------------------------------------------------------------------
// Kernel C: per-row attention from precomputed edge lists
// ---------------------------------------------------------------------------
__global__ void __launch_bounds__(256)
attn_kernel(float* __restrict__ out) {
    int n = blockIdx.x;
    int tid = threadIdx.x;
    int lane = tid & 31;
    int wid = tid >> 5;

    __shared__ unsigned s_list[CAP];
    __shared__ float s_p[3][CAP];
    __shared__ float s_al[3][4];
    __shared__ float s_red[3][8];
    __shared__ float s_mx[3];
    __shared__ float s_inv[3];

    if (tid < 12) {
        int k = tid >> 2, j = tid & 3;
        s_al[k][j] = g_al[((size_t)k * NN + n) * 4 + j];
    }

    int cnt = g_cnt[n];
    const unsigned* lst = g_list + (size_t)n * CAP;
    for (int e = tid; e < cnt; e += 256) s_list[e] = lst[e];
    __syncthreads();

    // ---- scores for all 3 k
    for (int e = tid; e < cnt; e += 256) {
        unsigned v = s_list[e];
        int m = (int)(v >> 6);
        int code = (int)(v & 63u);
#pragma unroll
        for (int k = 0; k < 3; k++) {
            float4 arv = *(const float4*)(g_ar + ((size_t)k * NN + m) * 4);
            float s = 0.f;
            if (code & 1) s += s_al[k][0] + arv.x;
            if (code & 2) s += s_al[k][1] + arv.y;
            if (code & 4) s += s_al[k][2] + arv.z;
            if (code & (8 << k)) s += s_al[k][3] + arv.w;
            s_p[k][e] = s;
        }
    }
    __syncthreads();

    // ---- max over valid (score != 0) per k
    float mx[3] = {-INFINITY, -INFINITY, -INFINITY};
    for (int e = tid; e < cnt; e += 256) {
#pragma unroll
        for (int k = 0; k < 3; k++) {
            float s = s_p[k][e];
            if (s != 0.f) mx[k] = fmaxf(mx[k], s);
        }
    }
#pragma unroll
    for (int k = 0; k < 3; k++)
#pragma unroll
        for (int o = 16; o; o >>= 1)
            mx[k] = fmaxf(mx[k], __shfl_xor_sync(0xffffffffu, mx[k], o));
    if (lane == 0) {
#pragma unroll
        for (int k = 0; k < 3; k++) s_red[k][wid] = mx[k];
    }
    __syncthreads();
    if (tid == 0) {
#pragma unroll
        for (int k = 0; k < 3; k++) {
            float m = s_red[k][0];
#pragma unroll
            for (int w = 1; w < 8; w++) m = fmaxf(m, s_red[k][w]);
            s_mx[k] = m;
        }
    }
    __syncthreads();

    // ---- exp + sum
    float mxk[3] = {s_mx[0], s_mx[1], s_mx[2]};
    float sm[3] = {0.f, 0.f, 0.f};
    for (int e = tid; e < cnt; e += 256) {
#pragma unroll
        for (int k = 0; k < 3; k++) {
            float s = s_p[k][e];
            float p = (s != 0.f) ? __expf(s - mxk[k]) : 0.f;
            s_p[k][e] = p;
            sm[k] += p;
        }
    }
#pragma unroll
    for (int k = 0; k < 3; k++)
#pragma unroll
        for (int o = 16; o; o >>= 1)
            sm[k] += __shfl_xor_sync(0xffffffffu, sm[k], o);
    if (lane == 0) {
#pragma unroll
        for (int k = 0; k < 3; k++) s_red[k][wid] = sm[k];
    }
    __syncthreads();
    if (tid == 0) {
#pragma unroll
        for (int k = 0; k < 3; k++) {
            float t = 0.f;
#pragma unroll
            for (int w = 0; w < 8; w++) t += s_red[k][w];
            s_inv[k] = (t > 0.f) ? (1.0f / t) : 0.f;
        }
    }
    __syncthreads();

    // ---- gather: thread = output channel d
    float acc0 = 0.f, acc1 = 0.f, acc2 = 0.f;
    const float* wxd = g_wx + tid;
#pragma unroll 2
    for (int e = 0; e < cnt; e++) {
        unsigned v = s_list[e];
        int m = (int)(v >> 6);
        float p0 = s_p[0][e];
        float p1 = s_p[1][e];
        float p2 = s_p[2][e];
        const float* base = wxd + (size_t)m * DOUT;
        if (p0 != 0.f) acc0 += p0 * base[0];
        if (p1 != 0.f) acc1 += p1 * base[(size_t)NN * DOUT];
        if (p2 != 0.f) acc2 += p2 * base[2 * (size_t)NN * DOUT];
    }

    float t = acc0 * s_inv[0] + acc1 * s_inv[1] + acc2 * s_inv[2];
    out[(size_t)n * DOUT + tid] = (t > 0.f) ? t : expm1f(t);
}

// ---------------------------------------------------------------------------
extern "C" void kernel_launch(void* const* d_in, const int* in_sizes, int n_in,
                              void* d_out, int out_size) {
    const float* x        = (const float*)d_in[0];
    const int*   supports = (const int*)d_in[1];
    const int*   atten    = (const int*)d_in[2];
    const float* Wt       = (const float*)d_in[3];
    const float* Wl       = (const float*)d_in[4];
    const float* Wr       = (const float*)d_in[5];
    float* out = (float*)d_out;

    fused_gemm_compact<<<GEMM_BLOCKS + NN, 256>>>(x, Wt, supports, atten);

    dim3 g2(NN / 32, KH);
    alar_kernel<<<g2, 256>>>(Wl, Wr);

    attn_kernel<<<NN, 256>>>(out);
}

// round 3
// speedup vs baseline: 1.2155x; 1.2155x over previous
#include <cuda_runtime.h>
#include <cuda_fp16.h>
#include <math.h>

#define NN 4096
#define DIN 256
#define DOUT 256
#define KH 3
#define CAP 512
#define GEMM_BLOCKS 768

// scratch (device globals: no allocation allowed)
__device__ float  g_wx[KH * NN * DOUT];          // 12 MB fp32 (for alar)
__device__ __half g_wxh[KH * NN * DOUT];         // 6 MB fp16 (for gather)
__device__ float  g_al[KH * NN * 4];
__device__ float  g_ar[KH * NN * 4];
__device__ unsigned g_list[NN * CAP];            // 8 MB edge lists
__device__ int g_cnt[NN];

// ---------------------------------------------------------------------------
// Kernel A: fused GEMM + mask compaction, STRIPED block mix (3 gemm : 16 comp)
// ---------------------------------------------------------------------------
__global__ void __launch_bounds__(256)
fused_gemm_compact(const float* __restrict__ x,
                   const float* __restrict__ Wt,
                   const int* __restrict__ supports,
                   const int* __restrict__ atten) {
    __shared__ float As[16][64];
    __shared__ float Bs[16][64];
    __shared__ int s_warp[8];

    int bid = blockIdx.x;               // 0 .. 4863  (= 19 * 256)
    int grp = bid / 19;
    int r   = bid % 19;
    int tx  = threadIdx.x;

    if (r < 3) {
        // ---------------- GEMM path ----------------
        int gid = grp * 3 + r;          // 0..767
        int k = gid >> 8;
        int rem = gid & 255;
        int row0 = (rem >> 2) * 64;
        int col0 = (rem & 3) * 64;
        const float* B = Wt + (size_t)k * DIN * DOUT;
        float*  C  = g_wx  + (size_t)k * NN * DOUT;
        __half* Ch = g_wxh + (size_t)k * NN * DOUT;

        int tr = tx >> 4;
        int tc = tx & 15;

        float acc[4][4];
#pragma unroll
        for (int i = 0; i < 4; i++)
#pragma unroll
            for (int j = 0; j < 4; j++) acc[i][j] = 0.f;

        for (int kk = 0; kk < DIN; kk += 16) {
            {
                int rr = tx >> 2;
                int c4 = (tx & 3) * 4;
                float4 v = *(const float4*)(x + (size_t)(row0 + rr) * DIN + kk + c4);
                As[c4 + 0][rr] = v.x;
                As[c4 + 1][rr] = v.y;
                As[c4 + 2][rr] = v.z;
                As[c4 + 3][rr] = v.w;
            }
            {
                int rr = tx >> 4;
                int cc = tx & 15;
                float4 w = *(const float4*)(B + (size_t)(kk + rr) * DOUT + col0 + cc * 4);
                *(float4*)&Bs[rr][cc * 4] = w;
            }
            __syncthreads();
#pragma unroll
            for (int p = 0; p < 16; p++) {
                float4 a = *(float4*)&As[p][tr * 4];
                float4 b = *(float4*)&Bs[p][tc * 4];
                float av[4] = {a.x, a.y, a.z, a.w};
                float bv[4] = {b.x, b.y, b.z, b.w};
#pragma unroll
                for (int i = 0; i < 4; i++)
#pragma unroll
                    for (int j = 0; j < 4; j++) acc[i][j] += av[i] * bv[j];
            }
            __syncthreads();
        }
#pragma unroll
        for (int i = 0; i < 4; i++) {
            size_t base = (size_t)(row0 + tr * 4 + i) * DOUT + col0 + tc * 4;
            float4 v = make_float4(acc[i][0], acc[i][1], acc[i][2], acc[i][3]);
            *(float4*)(C + base) = v;
            __half2 h0 = __floats2half2_rn(acc[i][0], acc[i][1]);
            __half2 h1 = __floats2half2_rn(acc[i][2], acc[i][3]);
            __half2* dh = (__half2*)(Ch + base);
            dh[0] = h0;
            dh[1] = h1;
        }
    } else {
        // ---------------- compaction path ----------------
        int n = grp * 16 + (r - 3);     // 0..4095
        int lane = tx & 31;
        int wid = tx >> 5;

        const int4* pa0 = (const int4*)(atten + ((size_t)0 * NN + n) * NN);
        const int4* pa1 = (const int4*)(atten + ((size_t)1 * NN + n) * NN);
        const int4* pa2 = (const int4*)(atten + ((size_t)2 * NN + n) * NN);
        const int4* ps0 = (const int4*)(supports + ((size_t)0 * NN + n) * NN);
        const int4* ps1 = (const int4*)(supports + ((size_t)1 * NN + n) * NN);
        const int4* ps2 = (const int4*)(supports + ((size_t)2 * NN + n) * NN);

        unsigned char codes[16];
        int cnt_local = 0;
#pragma unroll
        for (int it = 0; it < 4; it++) {
            int i = tx + it * 256;
            int4 a0 = pa0[i], a1 = pa1[i], a2 = pa2[i];
            int4 q0 = ps0[i], q1 = ps1[i], q2 = ps2[i];
            int aa0[4] = {a0.x, a0.y, a0.z, a0.w};
            int aa1[4] = {a1.x, a1.y, a1.z, a1.w};
            int aa2[4] = {a2.x, a2.y, a2.z, a2.w};
            int qq0[4] = {q0.x, q0.y, q0.z, q0.w};
            int qq1[4] = {q1.x, q1.y, q1.z, q1.w};
            int qq2[4] = {q2.x, q2.y, q2.z, q2.w};
#pragma unroll
            for (int j = 0; j < 4; j++) {
                int code = (aa0[j] ? 1 : 0) | (aa1[j] ? 2 : 0) | (aa2[j] ? 4 : 0) |
                           (qq0[j] ? 8 : 0) | (qq1[j] ? 16 : 0) | (qq2[j] ? 32 : 0);
                codes[it * 4 + j] = (unsigned char)code;
                cnt_local += (code != 0);
            }
        }

        int incl = cnt_local;
#pragma unroll
        for (int o = 1; o < 32; o <<= 1) {
            int t = __shfl_up_sync(0xffffffffu, incl, o);
            if (lane >= o) incl += t;
        }
        if (lane == 31) s_warp[wid] = incl;
        __syncthreads();
        if (tx < 8) {
            int t = s_warp[tx];
            int p = t;
#pragma unroll
            for (int o = 1; o < 8; o <<= 1) {
                int u = __shfl_up_sync(0xffu, p, o);
                if (tx >= o) p += u;
            }
            s_warp[tx] = p - t;
        }
        __syncthreads();
        int off = s_warp[wid] + incl - cnt_local;
        if (tx == 255) g_cnt[n] = min(off + cnt_local, CAP);

        unsigned* lst = g_list + (size_t)n * CAP;
#pragma unroll
        for (int it = 0; it < 4; it++) {
#pragma unroll
            for (int j = 0; j < 4; j++) {
                int c = codes[it * 4 + j];
                if (c) {
                    int m = (tx + it * 256) * 4 + j;
                    if (off < CAP) lst[off] = ((unsigned)m << 6) | (unsigned)c;
                    off++;
                }
            }
        }
    }
}

// ---------------------------------------------------------------------------
// Kernel B: al / ar projections
// ---------------------------------------------------------------------------
__global__ void alar_kernel(const float* __restrict__ Wl,
                            const float* __restrict__ Wr) {
    int k = blockIdx.y;
    int n0 = blockIdx.x * 32;
    __shared__ float sx[32][DOUT + 1];

    const float* wx = g_wx + (size_t)k * NN * DOUT;
    for (int i = threadIdx.x; i < 32 * (DOUT / 4); i += blockDim.x) {
        int rr = i / (DOUT / 4);
        int c = i % (DOUT / 4);
        float4 v = *(const float4*)(wx + (size_t)(n0 + rr) * DOUT + c * 4);
        sx[rr][c * 4 + 0] = v.x;
        sx[rr][c * 4 + 1] = v.y;
        sx[rr][c * 4 + 2] = v.z;
        sx[rr][c * 4 + 3] = v.w;
    }
    __syncthreads();

    int n = threadIdx.x >> 3;
    int j = threadIdx.x & 7;
    const float* w = (j < 4) ? (Wl + (size_t)(k * 4 + j) * DOUT)
                             : (Wr + (size_t)(k * 4 + (j - 4)) * DOUT);
    float s = 0.f;
#pragma unroll 8
    for (int d = 0; d < DOUT; d++) s += sx[n][d] * w[d];

    if (j < 4)
        g_al[((size_t)k * NN + n0 + n) * 4 + j] = s;
    else
        g_ar[((size_t)k * NN + n0 + n) * 4 + (j - 4)] = s;
}

// ---------------------------------------------------------------------------
// Kernel C: per-row attention; fp16 gather split across two thread halves
// ---------------------------------------------------------------------------
__global__ void __launch_bounds__(256)
attn_kernel(float* __restrict__ out) {
    int n = blockIdx.x;
    int tid = threadIdx.x;
    int lane = tid & 31;
    int wid = tid >> 5;

    __shared__ unsigned s_list[CAP];
    __shared__ float s_p[3][CAP];
    __shared__ float s_al[3][4];
    __shared__ float s_red[3][8];
    __shared__ float s_mx[3];
    __shared__ float s_inv[3];
    __shared__ float s_part[2][128][6];

    if (tid < 12) {
        int k = tid >> 2, j = tid & 3;
        s_al[k][j] = g_al[((size_t)k * NN + n) * 4 + j];
    }

    int cnt = g_cnt[n];
    const unsigned* lst = g_list + (size_t)n * CAP;
    for (int e = tid; e < cnt; e += 256) s_list[e] = lst[e];
    __syncthreads();

    // ---- scores for all 3 k
    for (int e = tid; e < cnt; e += 256) {
        unsigned v = s_list[e];
        int m = (int)(v >> 6);
        int code = (int)(v & 63u);
#pragma unroll
        for (int k = 0; k < 3; k++) {
            float4 arv = *(const float4*)(g_ar + ((size_t)k * NN + m) * 4);
            float s = 0.f;
            if (code & 1) s += s_al[k][0] + arv.x;
            if (code & 2) s += s_al[k][1] + arv.y;
            if (code & 4) s += s_al[k][2] + arv.z;
            if (code & (8 << k)) s += s_al[k][3] + arv.w;
            s_p[k][e] = s;
        }
    }
    __syncthreads();

    // ---- max over valid (score != 0) per k
    float mx[3] = {-INFINITY, -INFINITY, -INFINITY};
    for (int e = tid; e < cnt; e += 256) {
#pragma unroll
        for (int k = 0; k < 3; k++) {
            float s = s_p[k][e];
            if (s != 0.f) mx[k] = fmaxf(mx[k], s);
        }
    }
#pragma unroll
    for (int k = 0; k < 3; k++)
#pragma unroll
        for (int o = 16; o; o >>= 1)
            mx[k] = fmaxf(mx[k], __shfl_xor_sync(0xffffffffu, mx[k], o));
    if (lane == 0) {
#pragma unroll
        for (int k = 0; k < 3; k++) s_red[k][wid] = mx[k];
    }
    __syncthreads();
    if (tid == 0) {
#pragma unroll
        for (int k = 0; k < 3; k++) {
            float m = s_red[k][0];
#pragma unroll
            for (int w = 1; w < 8; w++) m = fmaxf(m, s_red[k][w]);
            s_mx[k] = m;
        }
    }
    __syncthreads();

    // ---- exp + sum
    float mxk[3] = {s_mx[0], s_mx[1], s_mx[2]};
    float sm[3] = {0.f, 0.f, 0.f};
    for (int e = tid; e < cnt; e += 256) {
#pragma unroll
        for (int k = 0; k < 3; k++) {
            float s = s_p[k][e];
            float p = (s != 0.f) ? __expf(s - mxk[k]) : 0.f;
            s_p[k][e] = p;
            sm[k] += p;
        }
    }
#pragma unroll
    for (int k = 0; k < 3; k++)
#pragma unroll
        for (int o = 16; o; o >>= 1)
            sm[k] += __shfl_xor_sync(0xffffffffu, sm[k], o);
    if (lane == 0) {
#pragma unroll
        for (int k = 0; k < 3; k++) s_red[k][wid] = sm[k];
    }
    __syncthreads();
    if (tid == 0) {
#pragma unroll
        for (int k = 0; k < 3; k++) {
            float t = 0.f;
#pragma unroll
            for (int w = 0; w < 8; w++) t += s_red[k][w];
            s_inv[k] = (t > 0.f) ? (1.0f / t) : 0.f;
        }
    }
    __syncthreads();

    // ---- gather (fp16 wx): two thread halves over edges, half2 channels
    int half_idx = tid >> 7;        // 0 or 1
    int l128 = tid & 127;           // channel pair index
    const __half2* wxh = (const __half2*)g_wxh;
    const size_t plane = (size_t)NN * (DOUT / 2);   // half2 stride per k

    float a00 = 0.f, a01 = 0.f, a10 = 0.f, a11 = 0.f, a20 = 0.f, a21 = 0.f;
    for (int e = half_idx; e < cnt; e += 2) {
        unsigned v = s_list[e];
        int m = (int)(v >> 6);
        size_t base = (size_t)m * (DOUT / 2) + l128;
        float p0 = s_p[0][e];
        float p1 = s_p[1][e];
        float p2 = s_p[2][e];
        if (p0 != 0.f) {
            float2 f = __half22float2(wxh[base]);
            a00 += p0 * f.x; a01 += p0 * f.y;
        }
        if (p1 != 0.f) {
            float2 f = __half22float2(wxh[base + plane]);
            a10 += p1 * f.x; a11 += p1 * f.y;
        }
        if (p2 != 0.f) {
            float2 f = __half22float2(wxh[base + 2 * plane]);
            a20 += p2 * f.x; a21 += p2 * f.y;
        }
    }
    s_part[half_idx][l128][0] = a00;
    s_part[half_idx][l128][1] = a01;
    s_part[half_idx][l128][2] = a10;
    s_part[half_idx][l128][3] = a11;
    s_part[half_idx][l128][4] = a20;
    s_part[half_idx][l128][5] = a21;
    __syncthreads();

    if (tid < 128) {
        float i0 = s_inv[0], i1 = s_inv[1], i2 = s_inv[2];
        float t0 = (s_part[0][tid][0] + s_part[1][tid][0]) * i0
                 + (s_part[0][tid][2] + s_part[1][tid][2]) * i1
                 + (s_part[0][tid][4] + s_part[1][tid][4]) * i2;
        float t1 = (s_part[0][tid][1] + s_part[1][tid][1]) * i0
                 + (s_part[0][tid][3] + s_part[1][tid][3]) * i1
                 + (s_part[0][tid][5] + s_part[1][tid][5]) * i2;
        float o0 = (t0 > 0.f) ? t0 : expm1f(t0);
        float o1 = (t1 > 0.f) ? t1 : expm1f(t1);
        float2 o = make_float2(o0, o1);
        *(float2*)(out + (size_t)n * DOUT + tid * 2) = o;
    }
}

// ---------------------------------------------------------------------------
extern "C" void kernel_launch(void* const* d_in, const int* in_sizes, int n_in,
                              void* d_out, int out_size) {
    const float* x        = (const float*)d_in[0];
    const int*   supports = (const int*)d_in[1];
    const int*   atten    = (const int*)d_in[2];
    const float* Wt       = (const float*)d_in[3];
    const float* Wl       = (const float*)d_in[4];
    const float* Wr       = (const float*)d_in[5];
    float* out = (float*)d_out;

    fused_gemm_compact<<<GEMM_BLOCKS + NN, 256>>>(x, Wt, supports, atten);

    dim3 g2(NN / 32, KH);
    alar_kernel<<<g2, 256>>>(Wl, Wr);

    attn_kernel<<<NN, 256>>>(out);
}

// round 4
// speedup vs baseline: 1.3398x; 1.1023x over previous
#include <cuda_runtime.h>
#include <cuda_fp16.h>
#include <math.h>

#define NN 4096
#define DIN 256
#define DOUT 256
#define KH 3
#define CAP 512
#define GEMM_BLOCKS 768

// scratch (device globals: no allocation allowed)
__device__ float  g_wx[KH * NN * DOUT];          // 12 MB fp32 (for alar)
__device__ __half g_wxh[KH * NN * DOUT];         // 6 MB fp16 (for gather)
__device__ float  g_al[KH * NN * 4];
__device__ float  g_ar[KH * NN * 4];
__device__ unsigned g_list[NN * CAP];            // 8 MB edge lists
__device__ int g_cnt[NN];

// ---------------------------------------------------------------------------
// Kernel A: fused GEMM + mask compaction, STRIPED block mix (3 gemm : 16 comp)
// ---------------------------------------------------------------------------
__global__ void __launch_bounds__(256)
fused_gemm_compact(const float* __restrict__ x,
                   const float* __restrict__ Wt,
                   const int* __restrict__ supports,
                   const int* __restrict__ atten) {
    __shared__ float As[16][64];
    __shared__ float Bs[16][64];
    __shared__ int s_warp[8];

    int bid = blockIdx.x;               // 0 .. 4863  (= 19 * 256)
    int grp = bid / 19;
    int r   = bid % 19;
    int tx  = threadIdx.x;

    if (r < 3) {
        // ---------------- GEMM path ----------------
        int gid = grp * 3 + r;          // 0..767
        int k = gid >> 8;
        int rem = gid & 255;
        int row0 = (rem >> 2) * 64;
        int col0 = (rem & 3) * 64;
        const float* B = Wt + (size_t)k * DIN * DOUT;
        float*  C  = g_wx  + (size_t)k * NN * DOUT;
        __half* Ch = g_wxh + (size_t)k * NN * DOUT;

        int tr = tx >> 4;
        int tc = tx & 15;

        float acc[4][4];
#pragma unroll
        for (int i = 0; i < 4; i++)
#pragma unroll
            for (int j = 0; j < 4; j++) acc[i][j] = 0.f;

        for (int kk = 0; kk < DIN; kk += 16) {
            {
                int rr = tx >> 2;
                int c4 = (tx & 3) * 4;
                float4 v = *(const float4*)(x + (size_t)(row0 + rr) * DIN + kk + c4);
                As[c4 + 0][rr] = v.x;
                As[c4 + 1][rr] = v.y;
                As[c4 + 2][rr] = v.z;
                As[c4 + 3][rr] = v.w;
            }
            {
                int rr = tx >> 4;
                int cc = tx & 15;
                float4 w = *(const float4*)(B + (size_t)(kk + rr) * DOUT + col0 + cc * 4);
                *(float4*)&Bs[rr][cc * 4] = w;
            }
            __syncthreads();
#pragma unroll
            for (int p = 0; p < 16; p++) {
                float4 a = *(float4*)&As[p][tr * 4];
                float4 b = *(float4*)&Bs[p][tc * 4];
                float av[4] = {a.x, a.y, a.z, a.w};
                float bv[4] = {b.x, b.y, b.z, b.w};
#pragma unroll
                for (int i = 0; i < 4; i++)
#pragma unroll
                    for (int j = 0; j < 4; j++) acc[i][j] += av[i] * bv[j];
            }
            __syncthreads();
        }
#pragma unroll
        for (int i = 0; i < 4; i++) {
            size_t base = (size_t)(row0 + tr * 4 + i) * DOUT + col0 + tc * 4;
            float4 v = make_float4(acc[i][0], acc[i][1], acc[i][2], acc[i][3]);
            *(float4*)(C + base) = v;
            __half2 h0 = __floats2half2_rn(acc[i][0], acc[i][1]);
            __half2 h1 = __floats2half2_rn(acc[i][2], acc[i][3]);
            __half2* dh = (__half2*)(Ch + base);
            dh[0] = h0;
            dh[1] = h1;
        }
    } else {
        // ---------------- compaction path ----------------
        int n = grp * 16 + (r - 3);     // 0..4095
        int lane = tx & 31;
        int wid = tx >> 5;

        const int4* pa0 = (const int4*)(atten + ((size_t)0 * NN + n) * NN);
        const int4* pa1 = (const int4*)(atten + ((size_t)1 * NN + n) * NN);
        const int4* pa2 = (const int4*)(atten + ((size_t)2 * NN + n) * NN);
        const int4* ps0 = (const int4*)(supports + ((size_t)0 * NN + n) * NN);
        const int4* ps1 = (const int4*)(supports + ((size_t)1 * NN + n) * NN);
        const int4* ps2 = (const int4*)(supports + ((size_t)2 * NN + n) * NN);

        unsigned char codes[16];
        int cnt_local = 0;
#pragma unroll
        for (int it = 0; it < 4; it++) {
            int i = tx + it * 256;
            int4 a0 = __ldcs(pa0 + i), a1 = __ldcs(pa1 + i), a2 = __ldcs(pa2 + i);
            int4 q0 = __ldcs(ps0 + i), q1 = __ldcs(ps1 + i), q2 = __ldcs(ps2 + i);
            int aa0[4] = {a0.x, a0.y, a0.z, a0.w};
            int aa1[4] = {a1.x, a1.y, a1.z, a1.w};
            int aa2[4] = {a2.x, a2.y, a2.z, a2.w};
            int qq0[4] = {q0.x, q0.y, q0.z, q0.w};
            int qq1[4] = {q1.x, q1.y, q1.z, q1.w};
            int qq2[4] = {q2.x, q2.y, q2.z, q2.w};
#pragma unroll
            for (int j = 0; j < 4; j++) {
                int code = (aa0[j] ? 1 : 0) | (aa1[j] ? 2 : 0) | (aa2[j] ? 4 : 0) |
                           (qq0[j] ? 8 : 0) | (qq1[j] ? 16 : 0) | (qq2[j] ? 32 : 0);
                codes[it * 4 + j] = (unsigned char)code;
                cnt_local += (code != 0);
            }
        }

        int incl = cnt_local;
#pragma unroll
        for (int o = 1; o < 32; o <<= 1) {
            int t = __shfl_up_sync(0xffffffffu, incl, o);
            if (lane >= o) incl += t;
        }
        if (lane == 31) s_warp[wid] = incl;
        __syncthreads();
        if (tx < 8) {
            int t = s_warp[tx];
            int p = t;
#pragma unroll
            for (int o = 1; o < 8; o <<= 1) {
                int u = __shfl_up_sync(0xffu, p, o);
                if (tx >= o) p += u;
            }
            s_warp[tx] = p - t;
        }
        __syncthreads();
        int off = s_warp[wid] + incl - cnt_local;
        if (tx == 255) g_cnt[n] = min(off + cnt_local, CAP);

        unsigned* lst = g_list + (size_t)n * CAP;
#pragma unroll
        for (int it = 0; it < 4; it++) {
#pragma unroll
            for (int j = 0; j < 4; j++) {
                int c = codes[it * 4 + j];
                if (c) {
                    int m = (tx + it * 256) * 4 + j;
                    if (off < CAP) lst[off] = ((unsigned)m << 6) | (unsigned)c;
                    off++;
                }
            }
        }
    }
}

// ---------------------------------------------------------------------------
// Kernel B: al / ar projections
// ---------------------------------------------------------------------------
__global__ void alar_kernel(const float* __restrict__ Wl,
                            const float* __restrict__ Wr) {
    int k = blockIdx.y;
    int n0 = blockIdx.x * 32;
    __shared__ float sx[32][DOUT + 1];

    const float* wx = g_wx + (size_t)k * NN * DOUT;
    for (int i = threadIdx.x; i < 32 * (DOUT / 4); i += blockDim.x) {
        int rr = i / (DOUT / 4);
        int c = i % (DOUT / 4);
        float4 v = *(const float4*)(wx + (size_t)(n0 + rr) * DOUT + c * 4);
        sx[rr][c * 4 + 0] = v.x;
        sx[rr][c * 4 + 1] = v.y;
        sx[rr][c * 4 + 2] = v.z;
        sx[rr][c * 4 + 3] = v.w;
    }
    __syncthreads();

    int n = threadIdx.x >> 3;
    int j = threadIdx.x & 7;
    const float* w = (j < 4) ? (Wl + (size_t)(k * 4 + j) * DOUT)
                             : (Wr + (size_t)(k * 4 + (j - 4)) * DOUT);
    float s = 0.f;
#pragma unroll 8
    for (int d = 0; d < DOUT; d++) s += sx[n][d] * w[d];

    if (j < 4)
        g_al[((size_t)k * NN + n0 + n) * 4 + j] = s;
    else
        g_ar[((size_t)k * NN + n0 + n) * 4 + (j - 4)] = s;
}

// ---------------------------------------------------------------------------
// Kernel C: per-row attention; per-k dense (m, p*inv) lists -> branch-free
// fp16 gather with high MLP.
// ---------------------------------------------------------------------------
__global__ void __launch_bounds__(256)
attn_kernel(float* __restrict__ out) {
    int n = blockIdx.x;
    int tid = threadIdx.x;
    int lane = tid & 31;
    int wid = tid >> 5;

    __shared__ unsigned s_list[CAP];
    __shared__ float s_p[3][CAP];
    __shared__ unsigned short s_mk[3 * CAP];
    __shared__ float s_pv[3 * CAP];
    __shared__ float s_al[3][4];
    __shared__ float s_red[3][8];
    __shared__ float s_mx[3];
    __shared__ float s_inv[3];
    __shared__ int s_warp[8];
    __shared__ int s_tot;                 // packed totals
    __shared__ float s_part[2][128][2];

    if (tid < 12) {
        int k = tid >> 2, j = tid & 3;
        s_al[k][j] = g_al[((size_t)k * NN + n) * 4 + j];
    }

    int cnt = g_cnt[n];
    const unsigned* lst = g_list + (size_t)n * CAP;
    for (int e = tid; e < cnt; e += 256) s_list[e] = lst[e];
    __syncthreads();

    // ---- phase 1: scores for all 3 k, track running max
    float mx[3] = {-INFINITY, -INFINITY, -INFINITY};
    for (int e = tid; e < cnt; e += 256) {
        unsigned v = s_list[e];
        int m = (int)(v >> 6);
        int code = (int)(v & 63u);
#pragma unroll
        for (int k = 0; k < 3; k++) {
            float4 arv = *(const float4*)(g_ar + ((size_t)k * NN + m) * 4);
            float s = 0.f;
            if (code & 1) s += s_al[k][0] + arv.x;
            if (code & 2) s += s_al[k][1] + arv.y;
            if (code & 4) s += s_al[k][2] + arv.z;
            if (code & (8 << k)) s += s_al[k][3] + arv.w;
            s_p[k][e] = s;
            if (s != 0.f) mx[k] = fmaxf(mx[k], s);
        }
    }
#pragma unroll
    for (int k = 0; k < 3; k++)
#pragma unroll
        for (int o = 16; o; o >>= 1)
            mx[k] = fmaxf(mx[k], __shfl_xor_sync(0xffffffffu, mx[k], o));
    if (lane == 0) {
#pragma unroll
        for (int k = 0; k < 3; k++) s_red[k][wid] = mx[k];
    }
    __syncthreads();
    if (tid == 0) {
#pragma unroll
        for (int k = 0; k < 3; k++) {
            float m = s_red[k][0];
#pragma unroll
            for (int w = 1; w < 8; w++) m = fmaxf(m, s_red[k][w]);
            s_mx[k] = m;
        }
    }
    __syncthreads();

    // ---- phase 2: exp + sum + per-k valid counts (p != 0 predicate)
    float mxk[3] = {s_mx[0], s_mx[1], s_mx[2]};
    float sm[3] = {0.f, 0.f, 0.f};
    int ck[3] = {0, 0, 0};
    for (int e = tid; e < cnt; e += 256) {
#pragma unroll
        for (int k = 0; k < 3; k++) {
            float s = s_p[k][e];
            float p = (s != 0.f) ? __expf(s - mxk[k]) : 0.f;
            s_p[k][e] = p;
            sm[k] += p;
            ck[k] += (p != 0.f);
        }
    }
#pragma unroll
    for (int k = 0; k < 3; k++)
#pragma unroll
        for (int o = 16; o; o >>= 1)
            sm[k] += __shfl_xor_sync(0xffffffffu, sm[k], o);
    if (lane == 0) {
#pragma unroll
        for (int k = 0; k < 3; k++) s_red[k][wid] = sm[k];
    }

    // packed prefix sum of per-k counts (10 bits each; max 512 per field)
    int packed = ck[0] | (ck[1] << 10) | (ck[2] << 20);
    int incl = packed;
#pragma unroll
    for (int o = 1; o < 32; o <<= 1) {
        int t = __shfl_up_sync(0xffffffffu, incl, o);
        if (lane >= o) incl += t;
    }
    if (lane == 31) s_warp[wid] = incl;
    __syncthreads();
    if (tid == 0) {
#pragma unroll
        for (int k = 0; k < 3; k++) {
            float t = 0.f;
#pragma unroll
            for (int w = 0; w < 8; w++) t += s_red[k][w];
            s_inv[k] = (t > 0.f) ? (1.0f / t) : 0.f;
        }
    }
    if (tid < 8) {
        int t = s_warp[tid];
        int p = t;
#pragma unroll
        for (int o = 1; o < 8; o <<= 1) {
            int u = __shfl_up_sync(0xffu, p, o);
            if (tid >= o) p += u;
        }
        s_warp[tid] = p - t;          // exclusive warp offset (packed)
        if (tid == 7) s_tot = p;      // grand totals (packed) via last warp incl
    }
    __syncthreads();

    // NOTE: s_tot written above is inclusive over warps of warp-totals == grand total
    int tot_packed = s_tot;
    int tot0 = tot_packed & 1023;
    int tot1 = (tot_packed >> 10) & 1023;
    int base_k[3];
    base_k[0] = 0;
    base_k[1] = tot0;
    base_k[2] = tot0 + tot1;

    int excl = s_warp[wid] + incl - packed;   // packed exclusive offset for this thread
    int offk[3];
    offk[0] = base_k[0] + (excl & 1023);
    offk[1] = base_k[1] + ((excl >> 10) & 1023);
    offk[2] = base_k[2] + ((excl >> 20) & 1023);

    // ---- phase 3: write dense (m, p*inv) lists
    float invk[3] = {s_inv[0], s_inv[1], s_inv[2]};
    for (int e = tid; e < cnt; e += 256) {
        unsigned m = s_list[e] >> 6;
#pragma unroll
        for (int k = 0; k < 3; k++) {
            float p = s_p[k][e];
            if (p != 0.f) {
                s_mk[offk[k]] = (unsigned short)m;
                s_pv[offk[k]] = p * invk[k];
                offk[k]++;
            }
        }
    }
    __syncthreads();

    // ---- phase 4: branch-free gather over dense lists
    int half_idx = tid >> 7;        // 0 or 1
    int l128 = tid & 127;           // half2 channel index
    const __half2* wxh = (const __half2*)g_wxh;

    float a0 = 0.f, a1 = 0.f;
    int tot2 = (tot_packed >> 20) & 1023;
    int totk[3] = {tot0, tot1, tot2};
#pragma unroll
    for (int k = 0; k < 3; k++) {
        const __half2* plane = wxh + (size_t)k * NN * (DOUT / 2) + l128;
        int b = base_k[k];
        int t = totk[k];
#pragma unroll 4
        for (int e = half_idx; e < t; e += 2) {
            float p = s_pv[b + e];
            int m = s_mk[b + e];
            float2 f = __half22float2(plane[(size_t)m * (DOUT / 2)]);
            a0 += p * f.x;
            a1 += p * f.y;
        }
    }
    s_part[half_idx][l128][0] = a0;
    s_part[half_idx][l128][1] = a1;
    __syncthreads();

    if (tid < 128) {
        float t0 = s_part[0][tid][0] + s_part[1][tid][0];
        float t1 = s_part[0][tid][1] + s_part[1][tid][1];
        float o0 = (t0 > 0.f) ? t0 : expm1f(t0);
        float o1 = (t1 > 0.f) ? t1 : expm1f(t1);
        *(float2*)(out + (size_t)n * DOUT + tid * 2) = make_float2(o0, o1);
    }
}

// ---------------------------------------------------------------------------
extern "C" void kernel_launch(void* const* d_in, const int* in_sizes, int n_in,
                              void* d_out, int out_size) {
    const float* x        = (const float*)d_in[0];
    const int*   supports = (const int*)d_in[1];
    const int*   atten    = (const int*)d_in[2];
    const float* Wt       = (const float*)d_in[3];
    const float* Wl       = (const float*)d_in[4];
    const float* Wr       = (const float*)d_in[5];
    float* out = (float*)d_out;

    fused_gemm_compact<<<GEMM_BLOCKS + NN, 256>>>(x, Wt, supports, atten);

    dim3 g2(NN / 32, KH);
    alar_kernel<<<g2, 256>>>(Wl, Wr);

    attn_kernel<<<NN, 256>>>(out);
}